// round 11
// baseline (speedup 1.0000x reference)
#include <cuda_runtime.h>
#include <cuda_bf16.h>
#include <math_constants.h>

// Problem constants
#define BB 16
#define CC 3
#define MM 512
#define NN 512
#define MNP (MM * NN)                 // 262144 pixels per (b, c) plane
#define PIX (BB * MNP)                // 4,194,304 pixels
#define THREADS 128
#define PIX_PER_THREAD 4
#define TILE_PX (THREADS * PIX_PER_THREAD)   // 512 pixels per tile
#define TILES (PIX / TILE_PX)                // 8192
#define GRID 820                             // 812 blocks x 10 tiles + 8 x 9 tiles
#define EPS_F 1e-6f
#define T1_CLIP_F 1e7f

// Fixed scratch for block partials (no allocation allowed)
__device__ float g_psum[GRID];
__device__ float g_pmax[GRID];
__device__ unsigned int g_count = 0;

__device__ __forceinline__ float rcp_approx(float x) {
    float y;
    asm("rcp.approx.f32 %0, %1;" : "=f"(y) : "f"(x));
    return y;
}

// Issue 9 coalesced 16B cp.async copies of this warp's 128-pixel sigma slab,
// then commit one group.  (128 px * 36 B = 4608 B per warp.)
__device__ __forceinline__ void issue_sigma(const float* __restrict__ sigma_y,
                                            int tl, float* smem_warp,
                                            int lane, int wid)
{
    const float* src = sigma_y + (size_t)(tl * TILE_PX + wid * 128) * 9;
    unsigned sw = (unsigned)__cvta_generic_to_shared(smem_warp);
#pragma unroll
    for (int k = 0; k < 9; k++) {
        const int f4 = k * 32 + lane;
        asm volatile("cp.async.cg.shared.global [%0], [%1], 16;"
                     :: "r"(sw + f4 * 16), "l"(src + f4 * 4) : "memory");
    }
    asm volatile("cp.async.commit_group;" ::: "memory");
}

// Issue (do not consume!) this warp's 24 coalesced streaming loads for
// target & mu; results land in tr[12]/mr[12] for later use.
__device__ __forceinline__ void issue_tm(const float* __restrict__ target,
                                         const float* __restrict__ mu,
                                         int tl, int lane, int wid,
                                         float* tr, float* mr)
{
    const int wb = tl * TILE_PX + wid * 128;
    const int b  = wb >> 18;
    const int r  = wb & (MNP - 1);
    const size_t base = (size_t)b * (CC * MNP) + r + lane;
#pragma unroll
    for (int j = 0; j < 4; j++) {
        const size_t o = base + j * 32;
        tr[j]     = __ldcs(target + o);
        tr[4 + j] = __ldcs(target + o + MNP);
        tr[8 + j] = __ldcs(target + o + 2 * MNP);
        mr[j]     = __ldcs(mu + o);
        mr[4 + j] = __ldcs(mu + o + MNP);
        mr[8 + j] = __ldcs(mu + o + 2 * MNP);
    }
}

// 4-pixel batched math: adjugate quadratic forms + 1 RCP + 1 LG2 per thread.
__device__ __forceinline__ void compute_tile(const float* sw, const float* tr,
                                             const float* mr, int lane,
                                             float& tsum, float& tmax)
{
    float qv[4], dc[4];
#pragma unroll
    for (int j = 0; j < 4; j++) {
        const float* s = sw + (lane + j * 32) * 9;  // stride 9 words: conflict-free
        const float a  = s[0], bq = s[1], c = s[2];
        const float d  = s[4], e  = s[5];
        const float f  = s[8];

        const float A00 = fmaf(d, f, -e * e);
        const float A01 = fmaf(c, e, -bq * f);
        const float A02 = fmaf(bq, e, -c * d);
        const float A11 = fmaf(a, f, -c * c);
        const float A12 = fmaf(bq, c, -a * e);
        const float A22 = fmaf(a, d, -bq * bq);

        const float det = fmaf(a, A00, fmaf(bq, A01, c * A02));

        const float x = tr[j]     - mr[j];
        const float y = tr[4 + j] - mr[4 + j];
        const float z = tr[8 + j] - mr[8 + j];

        float q = x * x * A00;
        q = fmaf(y * y, A11, q);
        q = fmaf(z * z, A22, q);
        float cross = x * y * A01;
        cross = fmaf(x * z, A02, cross);
        cross = fmaf(y * z, A12, cross);
        q = fmaf(2.0f, cross, q);

        qv[j] = q;
        dc[j] = fmaxf(det, EPS_F);   // SPD (>= 0.5 I) => clamp never binds
    }

    const float p01  = dc[0] * dc[1];
    const float p23  = dc[2] * dc[3];
    const float prod = p01 * p23;
    const float invp = rcp_approx(prod);

    const float t1v0 = 0.5f * qv[0] * (dc[1] * p23 * invp);
    const float t1v1 = 0.5f * qv[1] * (dc[0] * p23 * invp);
    const float t1v2 = 0.5f * qv[2] * (p01 * dc[3] * invp);
    const float t1v3 = 0.5f * qv[3] * (p01 * dc[2] * invp);

    tsum += (t1v0 + t1v1) + (t1v2 + t1v3) + 0.5f * __logf(prod);
    tmax  = fmaxf(tmax, fmaxf(fmaxf(t1v0, t1v1), fmaxf(t1v2, t1v3)));
}

__global__ __launch_bounds__(THREADS, 6) void maploss_main(
    const float* __restrict__ target,
    const float* __restrict__ mu,
    const float* __restrict__ sigma_y,
    float* __restrict__ out)
{
    // Double-buffered sigma staging: 2 x (4 warps x 128 px x 9 floats) = 36 KB
    __shared__ float s_sig[2][4 * 128 * 9];

    const int lane = threadIdx.x & 31;
    const int wid  = threadIdx.x >> 5;
    const int bid  = blockIdx.x;
    const int ntiles = (TILES - 1 - bid) / GRID + 1;   // 10 (or 9 for last 8 blocks)

    float* buf0 = &s_sig[0][wid * (128 * 9)];
    float* buf1 = &s_sig[1][wid * (128 * 9)];

    float trA[12], mrA[12], trB[12], mrB[12];
    float tsum = 0.0f;
    float tmax = -CUDART_INF_F;

    // Prologue: tile 0 in flight (buffer 0 / regs A)
    issue_sigma(sigma_y, bid, buf0, lane, wid);
    issue_tm(target, mu, bid, lane, wid, trA, mrA);

    for (int it = 0; it < ntiles; ++it) {
        const int tl = bid + it * GRID;
        const bool hasNext = (it + 1) < ntiles;
        if ((it & 1) == 0) {
            if (hasNext) {
                issue_sigma(sigma_y, tl + GRID, buf1, lane, wid);
                issue_tm(target, mu, tl + GRID, lane, wid, trB, mrB);
                asm volatile("cp.async.wait_group 1;" ::: "memory");
            } else {
                asm volatile("cp.async.wait_group 0;" ::: "memory");
            }
            __syncwarp();
            compute_tile(buf0, trA, mrA, lane, tsum, tmax);
        } else {
            if (hasNext) {
                issue_sigma(sigma_y, tl + GRID, buf0, lane, wid);
                issue_tm(target, mu, tl + GRID, lane, wid, trA, mrA);
                asm volatile("cp.async.wait_group 1;" ::: "memory");
            } else {
                asm volatile("cp.async.wait_group 0;" ::: "memory");
            }
            __syncwarp();
            compute_tile(buf1, trB, mrB, lane, tsum, tmax);
        }
    }

    // ---- block reduce (once per block, not per tile) ----
#pragma unroll
    for (int off = 16; off > 0; off >>= 1) {
        tsum += __shfl_down_sync(0xFFFFFFFFu, tsum, off);
        tmax  = fmaxf(tmax, __shfl_down_sync(0xFFFFFFFFu, tmax, off));
    }

    __shared__ float ssum[THREADS / 32];
    __shared__ float smax[THREADS / 32];
    if (lane == 0) { ssum[wid] = tsum; smax[wid] = tmax; }
    __syncthreads();

    if (wid == 0) {
        float s2 = (lane < THREADS / 32) ? ssum[lane] : 0.0f;
        float m2 = (lane < THREADS / 32) ? smax[lane] : -CUDART_INF_F;
#pragma unroll
        for (int off = 2; off > 0; off >>= 1) {
            s2 += __shfl_down_sync(0xFFFFFFFFu, s2, off);
            m2  = fmaxf(m2, __shfl_down_sync(0xFFFFFFFFu, m2, off));
        }
        if (lane == 0) {
            g_psum[bid] = s2;
            g_pmax[bid] = m2;
        }
    }

    // ---- fused finish: last block reduces all partials ----
    __shared__ bool is_last;
    __syncthreads();
    if (threadIdx.x == 0) {
        __threadfence();        // publish this block's partials
        unsigned int old = atomicAdd(&g_count, 1u);
        is_last = (old == (unsigned int)(GRID - 1));
    }
    __syncthreads();

    if (is_last) {
        if (threadIdx.x == 0) __threadfence();  // acquire: see all partials
        __syncthreads();
        float s = 0.0f;
        float m = -CUDART_INF_F;
#pragma unroll
        for (int i = 0; i < (GRID + THREADS - 1) / THREADS; i++) {
            const int idx = threadIdx.x + i * THREADS;
            if (idx < GRID) {
                s += __ldcg(&g_psum[idx]);
                m  = fmaxf(m, __ldcg(&g_pmax[idx]));
            }
        }
#pragma unroll
        for (int off = 16; off > 0; off >>= 1) {
            s += __shfl_down_sync(0xFFFFFFFFu, s, off);
            m  = fmaxf(m, __shfl_down_sync(0xFFFFFFFFu, m, off));
        }
        if (lane == 0) { ssum[wid] = s; smax[wid] = m; }
        __syncthreads();
        if (wid == 0) {
            float s2 = (lane < THREADS / 32) ? ssum[lane] : 0.0f;
            float m2 = (lane < THREADS / 32) ? smax[lane] : -CUDART_INF_F;
#pragma unroll
            for (int off = 2; off > 0; off >>= 1) {
                s2 += __shfl_down_sync(0xFFFFFFFFu, s2, off);
                m2  = fmaxf(m2, __shfl_down_sync(0xFFFFFFFFu, m2, off));
            }
            if (lane == 0) {
                const float mean = s2 * (1.0f / (float)PIX);
                out[0] = (m2 > T1_CLIP_F) ? 0.0f : mean;
                g_count = 0;   // reset ticket for next graph replay
            }
        }
    }
}

extern "C" void kernel_launch(void* const* d_in, const int* in_sizes, int n_in,
                              void* d_out, int out_size)
{
    // Input order per reference: target, mu, sigma_mu, sigma_n, sigma_y
    const float* target  = (const float*)d_in[0];
    const float* mu      = (const float*)d_in[1];
    const float* sigma_y = (const float*)d_in[4];
    float* out = (float*)d_out;

    maploss_main<<<GRID, THREADS>>>(target, mu, sigma_y, out);
}

// round 12
// speedup vs baseline: 1.0587x; 1.0587x over previous
#include <cuda_runtime.h>
#include <cuda_bf16.h>
#include <math_constants.h>

// Problem constants
#define BB 16
#define CC 3
#define MM 512
#define NN 512
#define MNP (MM * NN)                 // 262144 pixels per (b, c) plane
#define PIX (BB * MNP)                // 4,194,304 pixels
#define THREADS1 256
#define PIX_PER_THREAD 4
#define PIX_PER_BLOCK (THREADS1 * PIX_PER_THREAD)     // 1024
#define BLOCKS1 (PIX / PIX_PER_BLOCK)                 // 4096
#define EPS_F 1e-6f
#define T1_CLIP_F 1e7f

// Fixed scratch for block partials (no allocation allowed)
__device__ float g_psum[BLOCKS1];
__device__ float g_pmax[BLOCKS1];
__device__ unsigned int g_count = 0;

__device__ __forceinline__ float rcp_approx(float x) {
    float y;
    asm("rcp.approx.f32 %0, %1;" : "=f"(y) : "f"(x));
    return y;
}

// Streaming 128-bit global load
__device__ __forceinline__ float4 ldcs4(const float* p) {
    return __ldcs(reinterpret_cast<const float4*>(p));
}

__global__ __launch_bounds__(THREADS1) void maploss_main(
    const float* __restrict__ target,
    const float* __restrict__ mu,
    const float* __restrict__ sigma_y,
    float* __restrict__ out)
{
    // Warp-owned sigma staging: 8 warps * 128 px * 9 floats = 36 KB
    __shared__ float s_sig[THREADS1 * 9 * PIX_PER_THREAD];

    const int lane = threadIdx.x & 31;
    const int wid  = threadIdx.x >> 5;

    // Warp tile: 128 consecutive pixels; thread owns 4 CONSECUTIVE pixels.
    const int warpPixBase = blockIdx.x * PIX_PER_BLOCK + wid * 128;

    // ---- 1) cp.async staging of sigma (coalesced 16B chunks) ----
    {
        const float* src = sigma_y + (size_t)warpPixBase * 9;   // 4608 B / warp
        unsigned smem_w = (unsigned)__cvta_generic_to_shared(
            &s_sig[wid * (128 * 9)]);
#pragma unroll
        for (int k = 0; k < 9; k++) {
            const int f4 = k * 32 + lane;
            asm volatile("cp.async.cg.shared.global [%0], [%1], 16;"
                         :: "r"(smem_w + f4 * 16), "l"(src + f4 * 4) : "memory");
        }
        asm volatile("cp.async.commit_group;" ::: "memory");
    }

    // ---- 2) target/mu: 6 wide LDG.128 per thread (4 consecutive pixels) ----
    const int p0 = warpPixBase + lane * PIX_PER_THREAD;  // first pixel of thread
    const int b  = p0 >> 18;
    const int r  = p0 & (MNP - 1);
    const size_t base = (size_t)b * (CC * MNP) + r;

    float4 t0 = ldcs4(target + base);
    float4 t1 = ldcs4(target + base + MNP);
    float4 t2 = ldcs4(target + base + 2 * MNP);
    float4 u0 = ldcs4(mu + base);
    float4 u1 = ldcs4(mu + base + MNP);
    float4 u2 = ldcs4(mu + base + 2 * MNP);

    const float dx[4] = { t0.x - u0.x, t0.y - u0.y, t0.z - u0.z, t0.w - u0.w };
    const float dy[4] = { t1.x - u1.x, t1.y - u1.y, t1.z - u1.z, t1.w - u1.w };
    const float dz[4] = { t2.x - u2.x, t2.y - u2.y, t2.z - u2.z, t2.w - u2.w };

    // ---- 3) wait for sigma; per-thread 144B slab via LDS.128 (conflict-free) ----
    asm volatile("cp.async.wait_group 0;" ::: "memory");
    __syncwarp();

    // Thread's 36 sigma floats start at word 36*lane within the warp slab
    // (144B stride, 16B aligned -> 9 LDS.128, bank-conflict-free per phase).
    const float4* s4 = reinterpret_cast<const float4*>(
        &s_sig[wid * (128 * 9) + lane * 36]);
    float4 sv[9];
#pragma unroll
    for (int i = 0; i < 9; i++) sv[i] = s4[i];
    const float* sf = reinterpret_cast<const float*>(sv);

    float qv[4], dc[4];
#pragma unroll
    for (int j = 0; j < 4; j++) {
        const float* s = sf + 9 * j;   // row-major symmetric 3x3
        const float a  = s[0], bq = s[1], c = s[2];
        const float d  = s[4], e  = s[5];
        const float f  = s[8];

        const float A00 = fmaf(d, f, -e * e);
        const float A01 = fmaf(c, e, -bq * f);
        const float A02 = fmaf(bq, e, -c * d);
        const float A11 = fmaf(a, f, -c * c);
        const float A12 = fmaf(bq, c, -a * e);
        const float A22 = fmaf(a, d, -bq * bq);

        const float det = fmaf(a, A00, fmaf(bq, A01, c * A02));

        const float x = dx[j], y = dy[j], z = dz[j];
        float q = x * x * A00;
        q = fmaf(y * y, A11, q);
        q = fmaf(z * z, A22, q);
        float cross = x * y * A01;
        cross = fmaf(x * z, A02, cross);
        cross = fmaf(y * z, A12, cross);
        q = fmaf(2.0f, cross, q);

        qv[j] = q;
        dc[j] = fmaxf(det, EPS_F);   // SPD (>= 0.5 I) => clamp never binds
    }

    // ---- batched reciprocal + batched log: 1 RCP + 1 LG2 per 4 pixels ----
    const float p01  = dc[0] * dc[1];
    const float p23  = dc[2] * dc[3];
    const float prod = p01 * p23;
    const float invp = rcp_approx(prod);

    const float t1v0 = 0.5f * qv[0] * (dc[1] * p23 * invp);
    const float t1v1 = 0.5f * qv[1] * (dc[0] * p23 * invp);
    const float t1v2 = 0.5f * qv[2] * (p01 * dc[3] * invp);
    const float t1v3 = 0.5f * qv[3] * (p01 * dc[2] * invp);

    float sumv = (t1v0 + t1v1) + (t1v2 + t1v3) + 0.5f * __logf(prod);
    float maxv = fmaxf(fmaxf(t1v0, t1v1), fmaxf(t1v2, t1v3));

    // ---- warp reduce ----
#pragma unroll
    for (int off = 16; off > 0; off >>= 1) {
        sumv += __shfl_down_sync(0xFFFFFFFFu, sumv, off);
        maxv  = fmaxf(maxv, __shfl_down_sync(0xFFFFFFFFu, maxv, off));
    }

    __shared__ float ssum[THREADS1 / 32];
    __shared__ float smax[THREADS1 / 32];
    if (lane == 0) { ssum[wid] = sumv; smax[wid] = maxv; }
    __syncthreads();

    if (wid == 0) {
        float s2 = (lane < THREADS1 / 32) ? ssum[lane] : 0.0f;
        float m2 = (lane < THREADS1 / 32) ? smax[lane] : -CUDART_INF_F;
#pragma unroll
        for (int off = 4; off > 0; off >>= 1) {
            s2 += __shfl_down_sync(0xFFFFFFFFu, s2, off);
            m2  = fmaxf(m2, __shfl_down_sync(0xFFFFFFFFu, m2, off));
        }
        if (lane == 0) {
            g_psum[blockIdx.x] = s2;
            g_pmax[blockIdx.x] = m2;
        }
    }

    // ---- fused finish: last block reduces all partials ----
    __shared__ bool is_last;
    __syncthreads();
    if (threadIdx.x == 0) {
        __threadfence();        // publish this block's partials
        unsigned int old = atomicAdd(&g_count, 1u);
        is_last = (old == (unsigned int)(BLOCKS1 - 1));
    }
    __syncthreads();

    if (is_last) {
        if (threadIdx.x == 0) __threadfence();  // acquire: see all partials
        __syncthreads();
        float s = 0.0f;
        float m = -CUDART_INF_F;
#pragma unroll
        for (int i = 0; i < BLOCKS1 / THREADS1; i++) {
            const int idx = threadIdx.x + i * THREADS1;
            s += __ldcg(&g_psum[idx]);
            m  = fmaxf(m, __ldcg(&g_pmax[idx]));
        }
#pragma unroll
        for (int off = 16; off > 0; off >>= 1) {
            s += __shfl_down_sync(0xFFFFFFFFu, s, off);
            m  = fmaxf(m, __shfl_down_sync(0xFFFFFFFFu, m, off));
        }
        if (lane == 0) { ssum[wid] = s; smax[wid] = m; }
        __syncthreads();
        if (wid == 0) {
            float s2 = (lane < THREADS1 / 32) ? ssum[lane] : 0.0f;
            float m2 = (lane < THREADS1 / 32) ? smax[lane] : -CUDART_INF_F;
#pragma unroll
            for (int off = 4; off > 0; off >>= 1) {
                s2 += __shfl_down_sync(0xFFFFFFFFu, s2, off);
                m2  = fmaxf(m2, __shfl_down_sync(0xFFFFFFFFu, m2, off));
            }
            if (lane == 0) {
                const float mean = s2 * (1.0f / (float)PIX);
                out[0] = (m2 > T1_CLIP_F) ? 0.0f : mean;
                g_count = 0;   // reset ticket for next graph replay
            }
        }
    }
}

extern "C" void kernel_launch(void* const* d_in, const int* in_sizes, int n_in,
                              void* d_out, int out_size)
{
    // Input order per reference: target, mu, sigma_mu, sigma_n, sigma_y
    const float* target  = (const float*)d_in[0];
    const float* mu      = (const float*)d_in[1];
    const float* sigma_y = (const float*)d_in[4];
    float* out = (float*)d_out;

    maploss_main<<<BLOCKS1, THREADS1>>>(target, mu, sigma_y, out);
}